// round 10
// baseline (speedup 1.0000x reference)
#include <cuda_runtime.h>

// Integrate-and-fire, hard reset, scanned over time axis.
// x: [T=32, N] float32, out: [T=32, N] float32 (spikes 0/1).
// N = 4,194,304 neurons. Each thread owns 8 consecutive neurons (256-bit
// ld/st). T is processed in chunks of 8: a burst of 8 loads (8KB/warp read
// run), the scan chain in registers (spikes overwrite the input regs),
// then a burst of 8 stores (8KB/warp write run) — phase-separating the
// read and write streams to cut DRAM bus-turnaround overhead.

#define T_STEPS 32
#define T_CHUNK 8
#define V_TH 1.0f

__device__ __forceinline__ void ldg256(const float* p, float* r) {
    asm volatile(
        "ld.global.nc.v8.f32 {%0,%1,%2,%3,%4,%5,%6,%7}, [%8];"
        : "=f"(r[0]), "=f"(r[1]), "=f"(r[2]), "=f"(r[3]),
          "=f"(r[4]), "=f"(r[5]), "=f"(r[6]), "=f"(r[7])
        : "l"(p));
}

__device__ __forceinline__ void stg256(float* p, const float* r) {
    asm volatile(
        "st.global.cs.v8.f32 [%0], {%1,%2,%3,%4,%5,%6,%7,%8};"
        :: "l"(p),
           "f"(r[0]), "f"(r[1]), "f"(r[2]), "f"(r[3]),
           "f"(r[4]), "f"(r[5]), "f"(r[6]), "f"(r[7])
        : "memory");
}

__global__ __launch_bounds__(256) void if_scan_kernel(
    const float* __restrict__ x,
    float* __restrict__ out,
    int n8)   // number of 8-float lanes per timestep
{
    int i = blockIdx.x * blockDim.x + threadIdx.x;
    if (i >= n8) return;

    size_t elem = (size_t)i * 8;     // float offset within a timestep slice
    size_t stride = (size_t)n8 * 8;  // floats per timestep

    float m[8];
    #pragma unroll
    for (int k = 0; k < 8; k++) m[k] = 0.0f;

    #pragma unroll
    for (int tc = 0; tc < T_STEPS; tc += T_CHUNK) {
        float v[T_CHUNK][8];

        // read burst: 8 independent 256-bit loads
        #pragma unroll
        for (int tt = 0; tt < T_CHUNK; tt++) {
            size_t idx = (size_t)(tc + tt) * stride + elem;
            ldg256(x + idx, v[tt]);
        }

        // scan chain: spikes overwrite the input registers
        #pragma unroll
        for (int tt = 0; tt < T_CHUNK; tt++) {
            #pragma unroll
            for (int k = 0; k < 8; k++) {
                m[k] += v[tt][k];
                float s = (m[k] >= V_TH) ? 1.0f : 0.0f;
                m[k] = (s != 0.0f) ? 0.0f : m[k];
                v[tt][k] = s;
            }
        }

        // write burst: 8 back-to-back 256-bit stores
        #pragma unroll
        for (int tt = 0; tt < T_CHUNK; tt++) {
            size_t idx = (size_t)(tc + tt) * stride + elem;
            stg256(out + idx, v[tt]);
        }
    }
}

extern "C" void kernel_launch(void* const* d_in, const int* in_sizes, int n_in,
                              void* d_out, int out_size)
{
    const float* x = (const float*)d_in[0];
    float* out = (float*)d_out;

    int total = in_sizes[0];          // T * N
    int n = total / T_STEPS;          // neurons per timestep
    int n8 = n / 8;                   // 8-float lanes

    int threads = 256;
    int blocks = (n8 + threads - 1) / threads;

    if_scan_kernel<<<blocks, threads>>>(x, out, n8);
}